// round 1
// baseline (speedup 1.0000x reference)
#include <cuda_runtime.h>

// Problem constants
#define BATCH   16384
#define SEQ     4
#define DIM     512
#define ROWS    (BATCH * SEQ)       // 65536
#define HEADS   8
#define DH      64
#define GAMMA_F 0.4f
#define SCALE_F 0.044194173824159216f  // 512^-0.5

// Scratch (allocation-free rule: __device__ globals)
__device__ float g_Q [ROWS * DIM];        // 128 MiB
__device__ float g_KV[ROWS * 2 * DIM];    // 256 MiB
__device__ float g_AO[ROWS * DIM];        // 128 MiB

// ---------------------------------------------------------------------------
// SGEMM: C[M,N] = A[M,512] @ W[512,N] + bias[N]
// BM=128, BN=128, BK=16, 256 threads, 8x8 per thread.
// mode 0: C=g_Q, A=Aext ; mode 1: C=g_KV, A=Aext ; mode 2: A=g_AO, C=Cext
// ---------------------------------------------------------------------------
#define BM 128
#define BN 128
#define BK 16

__global__ __launch_bounds__(256) void sgemm_bias_kernel(
    const float* __restrict__ Aext,
    const float* __restrict__ W,
    const float* __restrict__ bias,
    float* __restrict__ Cext,
    int N, int mode)
{
    const float* A = (mode == 2) ? g_AO : Aext;
    float* C = (mode == 0) ? g_Q : (mode == 1) ? g_KV : Cext;
    const int K = DIM;

    __shared__ float As[BK][BM + 4];   // padded: conflict-free transposed stores
    __shared__ float Bs[BK][BN];

    const int tid = threadIdx.x;
    const int m0 = blockIdx.y * BM;
    const int n0 = blockIdx.x * BN;
    const int tx = tid & 15;
    const int ty = tid >> 4;

    float acc[8][8];
#pragma unroll
    for (int i = 0; i < 8; i++)
#pragma unroll
        for (int j = 0; j < 8; j++) acc[i][j] = 0.0f;

    for (int kt = 0; kt < K; kt += BK) {
        // Load A tile (128 x 16) transposed, and B tile (16 x 128)
#pragma unroll
        for (int l = 0; l < 2; l++) {
            int idx = tid + l * 256;
            int ar = idx >> 2;
            int ac = (idx & 3) * 4;
            float4 av = *(const float4*)&A[(size_t)(m0 + ar) * K + kt + ac];
            As[ac + 0][ar] = av.x;
            As[ac + 1][ar] = av.y;
            As[ac + 2][ar] = av.z;
            As[ac + 3][ar] = av.w;

            int br = idx >> 5;
            int bc = (idx & 31) * 4;
            float4 bv = *(const float4*)&W[(size_t)(kt + br) * N + n0 + bc];
            *(float4*)&Bs[br][bc] = bv;
        }
        __syncthreads();

#pragma unroll
        for (int kk = 0; kk < BK; kk++) {
            float a[8], b[8];
            *(float4*)&a[0] = *(const float4*)&As[kk][ty * 4];
            *(float4*)&a[4] = *(const float4*)&As[kk][64 + ty * 4];
            *(float4*)&b[0] = *(const float4*)&Bs[kk][tx * 4];
            *(float4*)&b[4] = *(const float4*)&Bs[kk][64 + tx * 4];
#pragma unroll
            for (int i = 0; i < 8; i++)
#pragma unroll
                for (int j = 0; j < 8; j++)
                    acc[i][j] += a[i] * b[j];
        }
        __syncthreads();
    }

    // Epilogue: add bias, store float4
#pragma unroll
    for (int i = 0; i < 8; i++) {
        int r = m0 + ((i < 4) ? (ty * 4 + i) : (64 + ty * 4 + (i - 4)));
#pragma unroll
        for (int jj = 0; jj < 2; jj++) {
            int c = n0 + jj * 64 + tx * 4;
            float4 o;
            o.x = acc[i][jj * 4 + 0] + bias[c + 0];
            o.y = acc[i][jj * 4 + 1] + bias[c + 1];
            o.z = acc[i][jj * 4 + 2] + bias[c + 2];
            o.w = acc[i][jj * 4 + 3] + bias[c + 3];
            *(float4*)&C[(size_t)r * N + c] = o;
        }
    }
}

// ---------------------------------------------------------------------------
// Attention: one warp per (batch, head). N=4 queries/keys, dh=64.
// Mask zeroes exactly j = 3 - i (dist = sqrt2); masked score = -(j+1)*gamma
// which PARTICIPATES in the softmax denominator; prob zeroed after softmax.
// Lane l owns dims l and l+32.
// ---------------------------------------------------------------------------
__global__ __launch_bounds__(256) void attn_kernel()
{
    int gwarp = blockIdx.x * 8 + (threadIdx.x >> 5);
    int lane = threadIdx.x & 31;
    if (gwarp >= BATCH * HEADS) return;
    int b = gwarp >> 3;
    int h = gwarp & 7;

    const float* qb  = g_Q  + (size_t)b * SEQ * DIM      + h * DH;
    const float* kvb = g_KV + (size_t)b * SEQ * (2 * DIM) + h * DH;

    float q0[4], q1[4], k0[4], k1[4], v0[4], v1[4];
#pragma unroll
    for (int i = 0; i < 4; i++) {
        q0[i] = qb[i * DIM + lane];
        q1[i] = qb[i * DIM + 32 + lane];
        k0[i] = kvb[i * (2 * DIM) + lane];
        k1[i] = kvb[i * (2 * DIM) + 32 + lane];
        v0[i] = kvb[i * (2 * DIM) + DIM + lane];
        v1[i] = kvb[i * (2 * DIM) + DIM + 32 + lane];
    }

    float s[4][4];
#pragma unroll
    for (int i = 0; i < 4; i++) {
#pragma unroll
        for (int j = 0; j < 4; j++) {
            float p = q0[i] * k0[j] + q1[i] * k1[j];
#pragma unroll
            for (int o = 16; o > 0; o >>= 1)
                p += __shfl_xor_sync(0xFFFFFFFFu, p, o);
            s[i][j] = p * SCALE_F;
        }
    }

#pragma unroll
    for (int i = 0; i < 4; i++) {
        int jm = 3 - i;                       // masked partner
        s[i][jm] = -(float)(jm + 1) * GAMMA_F; // finite bias, in denominator

        float mx = fmaxf(fmaxf(s[i][0], s[i][1]), fmaxf(s[i][2], s[i][3]));
        float e[4], sum = 0.0f;
#pragma unroll
        for (int j = 0; j < 4; j++) { e[j] = expf(s[i][j] - mx); sum += e[j]; }
        float inv = 1.0f / sum;
        float p[4];
#pragma unroll
        for (int j = 0; j < 4; j++) p[j] = e[j] * inv;
        p[jm] = 0.0f;                          // post-softmax mask

        float o0 = 0.0f, o1 = 0.0f;
#pragma unroll
        for (int j = 0; j < 4; j++) { o0 += p[j] * v0[j]; o1 += p[j] * v1[j]; }

        float* dst = g_AO + (size_t)(b * SEQ + i) * DIM + h * DH;
        dst[lane] = o0;
        dst[32 + lane] = o1;
    }
}

// ---------------------------------------------------------------------------
// Launch: q = x@Wq+bq ; kv = ctx@Wkv+bkv ; attention ; out = ao@Wo+bo
// ---------------------------------------------------------------------------
extern "C" void kernel_launch(void* const* d_in, const int* in_sizes, int n_in,
                              void* d_out, int out_size)
{
    const float* x    = (const float*)d_in[0];
    const float* ctx  = (const float*)d_in[1];
    const float* Wq   = (const float*)d_in[2];
    const float* bq   = (const float*)d_in[3];
    const float* Wkv  = (const float*)d_in[4];
    const float* bkv  = (const float*)d_in[5];
    const float* Wo   = (const float*)d_in[6];
    const float* bo   = (const float*)d_in[7];
    float* out = (float*)d_out;

    dim3 blk(256);

    // Q = x @ Wq + bq   -> g_Q
    sgemm_bias_kernel<<<dim3(DIM / BN, ROWS / BM), blk>>>(x, Wq, bq, nullptr, DIM, 0);
    // KV = ctx @ Wkv + bkv -> g_KV
    sgemm_bias_kernel<<<dim3(2 * DIM / BN, ROWS / BM), blk>>>(ctx, Wkv, bkv, nullptr, 2 * DIM, 1);
    // Attention -> g_AO  (131072 warps, 8 warps/block)
    attn_kernel<<<BATCH * HEADS / 8, blk>>>();
    // out = g_AO @ Wo + bo
    sgemm_bias_kernel<<<dim3(DIM / BN, ROWS / BM), blk>>>(nullptr, Wo, bo, out, DIM, 2);
}

// round 3
// speedup vs baseline: 1.3002x; 1.3002x over previous
#include <cuda_runtime.h>
#include <cstdint>

// ---------------- problem constants ----------------
#define BATCH   16384
#define SEQ     4
#define DIM     512
#define ROWS    (BATCH * SEQ)      // 65536
#define HEADS   8
#define GAMMA_F 0.4f
#define SCALE_F 0.044194173824159216f  // 512^-0.5

// scratch (allocation-free rule)
__device__ float g_Q [ROWS * DIM];
__device__ float g_KV[ROWS * 2 * DIM];
__device__ float g_AO[ROWS * DIM];

// ---------------- GEMM tiling ----------------
#define BM 128
#define BN 128
#define BK 32
#define NKT (DIM / BK)          // 16 k-tiles
#define PA 36                   // A smem pitch (floats): conflict-free frag loads
#define PB 132                  // B smem pitch (floats)
#define AS_FLOATS (BM * PA)     // 4608
#define BS_FLOATS (BK * PB)     // 4224
#define SMEM_FLOATS (2 * AS_FLOATS + 2 * BS_FLOATS)
#define SMEM_BYTES (SMEM_FLOATS * 4)   // 70656

__device__ __forceinline__ uint32_t f2tf32(float x) {
    uint32_t u;
    asm("cvt.rna.tf32.f32 %0, %1;" : "=r"(u) : "f"(x));
    return u;
}

__device__ __forceinline__ void mma_tf32(
    float c[4], uint32_t a0, uint32_t a1, uint32_t a2, uint32_t a3,
    uint32_t b0, uint32_t b1)
{
    asm volatile(
        "mma.sync.aligned.m16n8k8.row.col.f32.tf32.tf32.f32 "
        "{%0,%1,%2,%3}, {%4,%5,%6,%7}, {%8,%9}, {%0,%1,%2,%3};"
        : "+f"(c[0]), "+f"(c[1]), "+f"(c[2]), "+f"(c[3])
        : "r"(a0), "r"(a1), "r"(a2), "r"(a3), "r"(b0), "r"(b1));
}

// ---------------- producer helpers ----------------
__device__ __forceinline__ void ldg_tiles(
    const float* __restrict__ A, const float* __restrict__ W, int ldN,
    int m0, int n0, int t, int tid, float4 rA[4], float4 rB[4])
{
#pragma unroll
    for (int j = 0; j < 4; j++) {
        int idx = tid + j * 256;
        rA[j] = *(const float4*)&A[(size_t)(m0 + (idx >> 3)) * DIM + t * BK + (idx & 7) * 4];
    }
#pragma unroll
    for (int j = 0; j < 4; j++) {
        int idx = tid + j * 256;
        rB[j] = *(const float4*)&W[(size_t)(t * BK + (idx >> 5)) * ldN + n0 + (idx & 31) * 4];
    }
}

__device__ __forceinline__ void sts_tiles(
    float* As, float* Bs, int tid, const float4 rA[4], const float4 rB[4])
{
#pragma unroll
    for (int j = 0; j < 4; j++) {
        int idx = tid + j * 256;
        uint32_t* p = (uint32_t*)&As[(idx >> 3) * PA + (idx & 7) * 4];
        p[0] = f2tf32(rA[j].x); p[1] = f2tf32(rA[j].y);
        p[2] = f2tf32(rA[j].z); p[3] = f2tf32(rA[j].w);
    }
#pragma unroll
    for (int j = 0; j < 4; j++) {
        int idx = tid + j * 256;
        uint32_t* p = (uint32_t*)&Bs[(idx >> 5) * PB + (idx & 31) * 4];
        p[0] = f2tf32(rB[j].x); p[1] = f2tf32(rB[j].y);
        p[2] = f2tf32(rB[j].z); p[3] = f2tf32(rB[j].w);
    }
}

// ---------------- tf32 mma.sync GEMM: C[M,N] = A[M,512] @ W[512,N] + bias ----------------
__global__ __launch_bounds__(256, 1) void gemm_mma(
    const float* __restrict__ Aext, const float* __restrict__ W,
    const float* __restrict__ bias, float* __restrict__ Cext,
    int ldN, int mode)
{
    extern __shared__ float sm[];
    float* As[2] = { sm, sm + AS_FLOATS };
    float* Bs[2] = { sm + 2 * AS_FLOATS, sm + 2 * AS_FLOATS + BS_FLOATS };

    const float* A = (mode == 2) ? g_AO : Aext;
    float* C = (mode == 0) ? g_Q : (mode == 1) ? g_KV : Cext;

    const int tid = threadIdx.x;
    const int wid = tid >> 5;
    const int lane = tid & 31;
    const int g = lane >> 2;        // mma group id (0..7)
    const int t4 = lane & 3;        // mma thread-in-group (0..3)
    const int warp_m = wid >> 1;    // 0..3  (32 rows each)
    const int warp_n = wid & 1;     // 0..1  (64 cols each)
    const int m0 = blockIdx.y * BM;
    const int n0 = blockIdx.x * BN;

    float acc[2][8][4];
#pragma unroll
    for (int mf = 0; mf < 2; mf++)
#pragma unroll
        for (int nf = 0; nf < 8; nf++)
#pragma unroll
            for (int c = 0; c < 4; c++) acc[mf][nf][c] = 0.0f;

    float4 rA[4], rB[4];
    ldg_tiles(A, W, ldN, m0, n0, 0, tid, rA, rB);
    sts_tiles(As[0], Bs[0], tid, rA, rB);
    __syncthreads();

    for (int kt = 0; kt < NKT; kt++) {
        const int buf = kt & 1;
        if (kt + 1 < NKT)
            ldg_tiles(A, W, ldN, m0, n0, kt + 1, tid, rA, rB);

        const float* Ab = As[buf];
        const float* Bb = Bs[buf];
#pragma unroll
        for (int ks = 0; ks < 4; ks++) {
            const int k0 = ks * 8;
            uint32_t a[2][4];
#pragma unroll
            for (int mf = 0; mf < 2; mf++) {
                int rb = warp_m * 32 + mf * 16 + g;
                a[mf][0] = __float_as_uint(Ab[(size_t)rb * PA + k0 + t4]);
                a[mf][1] = __float_as_uint(Ab[(size_t)(rb + 8) * PA + k0 + t4]);
                a[mf][2] = __float_as_uint(Ab[(size_t)rb * PA + k0 + t4 + 4]);
                a[mf][3] = __float_as_uint(Ab[(size_t)(rb + 8) * PA + k0 + t4 + 4]);
            }
#pragma unroll
            for (int nf = 0; nf < 8; nf++) {
                int nc = warp_n * 64 + nf * 8 + g;
                uint32_t b0 = __float_as_uint(Bb[(size_t)(k0 + t4) * PB + nc]);
                uint32_t b1 = __float_as_uint(Bb[(size_t)(k0 + t4 + 4) * PB + nc]);
                mma_tf32(acc[0][nf], a[0][0], a[0][1], a[0][2], a[0][3], b0, b1);
                mma_tf32(acc[1][nf], a[1][0], a[1][1], a[1][2], a[1][3], b0, b1);
            }
        }

        if (kt + 1 < NKT)
            sts_tiles(As[buf ^ 1], Bs[buf ^ 1], tid, rA, rB);
        __syncthreads();
    }

    // epilogue: bias + store (c0,c1 @ row, c2,c3 @ row+8), float2 each
#pragma unroll
    for (int mf = 0; mf < 2; mf++) {
        int row = m0 + warp_m * 32 + mf * 16 + g;
#pragma unroll
        for (int nf = 0; nf < 8; nf++) {
            int col = n0 + warp_n * 64 + nf * 8 + 2 * t4;
            float b0 = bias[col], b1 = bias[col + 1];
            float2 o0 = make_float2(acc[mf][nf][0] + b0, acc[mf][nf][1] + b1);
            float2 o1 = make_float2(acc[mf][nf][2] + b0, acc[mf][nf][3] + b1);
            *(float2*)&C[(size_t)row * ldN + col] = o0;
            *(float2*)&C[(size_t)(row + 8) * ldN + col] = o1;
        }
    }
}

// ---------------- attention: one warp per (batch, head) ----------------
__global__ __launch_bounds__(256) void attn_kernel()
{
    int gwarp = blockIdx.x * 8 + (threadIdx.x >> 5);
    int lane = threadIdx.x & 31;
    if (gwarp >= BATCH * HEADS) return;
    int b = gwarp >> 3;
    int h = gwarp & 7;

    const float* qb  = g_Q  + (size_t)b * SEQ * DIM       + h * 64;
    const float* kvb = g_KV + (size_t)b * SEQ * (2 * DIM) + h * 64;

    float q0[4], q1[4], k0[4], k1[4], v0[4], v1[4];
#pragma unroll
    for (int i = 0; i < 4; i++) {
        q0[i] = qb[i * DIM + lane];
        q1[i] = qb[i * DIM + 32 + lane];
        k0[i] = kvb[i * (2 * DIM) + lane];
        k1[i] = kvb[i * (2 * DIM) + 32 + lane];
        v0[i] = kvb[i * (2 * DIM) + DIM + lane];
        v1[i] = kvb[i * (2 * DIM) + DIM + 32 + lane];
    }

    float s[4][4];
#pragma unroll
    for (int i = 0; i < 4; i++) {
#pragma unroll
        for (int j = 0; j < 4; j++) {
            float p = q0[i] * k0[j] + q1[i] * k1[j];
#pragma unroll
            for (int o = 16; o > 0; o >>= 1)
                p += __shfl_xor_sync(0xFFFFFFFFu, p, o);
            s[i][j] = p * SCALE_F;
        }
    }

#pragma unroll
    for (int i = 0; i < 4; i++) {
        int jm = 3 - i;                         // masked pair (dist = sqrt2)
        s[i][jm] = -(float)(jm + 1) * GAMMA_F;  // finite bias, stays in denominator

        float mx = fmaxf(fmaxf(s[i][0], s[i][1]), fmaxf(s[i][2], s[i][3]));
        float e[4], sum = 0.0f;
#pragma unroll
        for (int j = 0; j < 4; j++) { e[j] = expf(s[i][j] - mx); sum += e[j]; }
        float inv = 1.0f / sum;
        float p[4];
#pragma unroll
        for (int j = 0; j < 4; j++) p[j] = e[j] * inv;
        p[jm] = 0.0f;                           // post-softmax mask

        float o0 = 0.0f, o1 = 0.0f;
#pragma unroll
        for (int j = 0; j < 4; j++) { o0 += p[j] * v0[j]; o1 += p[j] * v1[j]; }

        float* dst = g_AO + (size_t)(b * SEQ + i) * DIM + h * 64;
        dst[lane] = o0;
        dst[32 + lane] = o1;
    }
}

// ---------------- launch ----------------
extern "C" void kernel_launch(void* const* d_in, const int* in_sizes, int n_in,
                              void* d_out, int out_size)
{
    const float* x   = (const float*)d_in[0];
    const float* ctx = (const float*)d_in[1];
    const float* Wq  = (const float*)d_in[2];
    const float* bq  = (const float*)d_in[3];
    const float* Wkv = (const float*)d_in[4];
    const float* bkv = (const float*)d_in[5];
    const float* Wo  = (const float*)d_in[6];
    const float* bo  = (const float*)d_in[7];
    float* out = (float*)d_out;

    cudaFuncSetAttribute(gemm_mma, cudaFuncAttributeMaxDynamicSharedMemorySize, SMEM_BYTES);

    // Q = x @ Wq + bq
    gemm_mma<<<dim3(DIM / BN, ROWS / BM), 256, SMEM_BYTES>>>(x, Wq, bq, nullptr, DIM, 0);
    // KV = ctx @ Wkv + bkv
    gemm_mma<<<dim3(2 * DIM / BN, ROWS / BM), 256, SMEM_BYTES>>>(ctx, Wkv, bkv, nullptr, 2 * DIM, 1);
    // attention
    attn_kernel<<<BATCH * HEADS / 8, 256>>>();
    // out = AO @ Wo + bo
    gemm_mma<<<dim3(DIM / BN, ROWS / BM), 256, SMEM_BYTES>>>(nullptr, Wo, bo, out, DIM, 2);
}

// round 4
// speedup vs baseline: 2.7821x; 2.1397x over previous
#include <cuda_runtime.h>
#include <cstdint>

// ---------------- problem constants ----------------
#define BATCH   16384
#define SEQ     4
#define DIM     512
#define ROWS    (BATCH * SEQ)      // 65536
#define HEADS   8
#define GAMMA_F 0.4f
#define SCALE_F 0.044194173824159216f  // 512^-0.5

// scratch (allocation-free rule)
__device__ float g_Q [ROWS * DIM];
__device__ float g_KV[ROWS * 2 * DIM];
__device__ float g_AO[ROWS * DIM];

// ---------------- GEMM tiling ----------------
#define BM 128
#define BN 128
#define BK 32
#define NKT (DIM / BK)              // 16 k-tiles
#define STAGES 3
#define A_STAGE 16384               // 128 rows x 128B (32 fp32), XOR-swizzled
#define B_STAGE 16384               // 32 rows x 512B (128 fp32), XOR-swizzled
#define STAGE_BYTES (A_STAGE + B_STAGE)
#define SMEM_BYTES (STAGES * STAGE_BYTES)   // 98304 -> 2 CTA/SM (192KB < 228KB)

__device__ __forceinline__ uint32_t smem_u32(const void* p) {
    uint32_t a;
    asm("{ .reg .u64 t; cvta.to.shared.u64 t, %1; cvt.u32.u64 %0, t; }"
        : "=r"(a) : "l"(p));
    return a;
}
__device__ __forceinline__ uint32_t f2tf32(float x) {
    uint32_t u;
    asm("cvt.rna.tf32.f32 %0, %1;" : "=r"(u) : "f"(x));
    return u;
}
__device__ __forceinline__ uint32_t lds_tf32(uint32_t addr) {
    float v;
    asm volatile("ld.shared.b32 %0, [%1];" : "=f"(v) : "r"(addr));
    return f2tf32(v);
}
__device__ __forceinline__ void cp16(uint32_t dst, const float* src) {
    asm volatile("cp.async.cg.shared.global [%0], [%1], 16;"
                 :: "r"(dst), "l"(src));
}
__device__ __forceinline__ void cp_commit() {
    asm volatile("cp.async.commit_group;");
}
template <int N>
__device__ __forceinline__ void cp_wait() {
    asm volatile("cp.async.wait_group %0;" :: "n"(N));
}

__device__ __forceinline__ void mma_tf32(
    float c[4], uint32_t a0, uint32_t a1, uint32_t a2, uint32_t a3,
    uint32_t b0, uint32_t b1)
{
    asm volatile(
        "mma.sync.aligned.m16n8k8.row.col.f32.tf32.tf32.f32 "
        "{%0,%1,%2,%3}, {%4,%5,%6,%7}, {%8,%9}, {%0,%1,%2,%3};"
        : "+f"(c[0]), "+f"(c[1]), "+f"(c[2]), "+f"(c[3])
        : "r"(a0), "r"(a1), "r"(a2), "r"(a3), "r"(b0), "r"(b1));
}

// issue cp.async for one k-tile t into stage (sA, sB)
__device__ __forceinline__ void issue_copy(
    uint32_t sA, uint32_t sB,
    const float* __restrict__ A, const float* __restrict__ W, int ldN,
    int m0, int n0, int t, int tid)
{
    // A tile: 128 rows x 8 granules(16B). swizzle: granule ^= (row & 7)
#pragma unroll
    for (int j = 0; j < 4; j++) {
        int g = tid + j * 256;
        int r = g >> 3, c = g & 7;
        uint32_t dst = sA + r * 128 + ((c ^ (r & 7)) << 4);
        cp16(dst, &A[(size_t)(m0 + r) * DIM + t * BK + c * 4]);
    }
    // B tile: 32 rows x 32 granules(16B). swizzle: granule ^= (row & 3) * 2
#pragma unroll
    for (int j = 0; j < 4; j++) {
        int g = tid + j * 256;
        int r = g >> 5, c = g & 31;
        uint32_t dst = sB + r * 512 + ((c ^ ((r & 3) << 1)) << 4);
        cp16(dst, &W[(size_t)(t * BK + r) * ldN + n0 + c * 4]);
    }
}

// ---------------- tf32 mma.sync GEMM: C[M,N] = A[M,512] @ W[512,N] + bias ----------------
__global__ __launch_bounds__(256, 2) void gemm_mma(
    const float* __restrict__ Aext, const float* __restrict__ W,
    const float* __restrict__ bias, float* __restrict__ Cext,
    int ldN, int mode)
{
    extern __shared__ float smf[];
    const uint32_t smb = smem_u32(smf);

    const float* A = (mode == 2) ? g_AO : Aext;
    float* C = (mode == 0) ? g_Q : (mode == 1) ? g_KV : Cext;

    const int tid = threadIdx.x;
    const int wid = tid >> 5;
    const int lane = tid & 31;
    const int g8 = lane >> 2;       // 0..7
    const int t4 = lane & 3;        // 0..3
    const int warp_m = wid >> 1;    // 0..3
    const int warp_n = wid & 1;     // 0..1
    const int m0 = blockIdx.y * BM;
    const int n0 = blockIdx.x * BN;

    float acc[2][8][4];
#pragma unroll
    for (int mf = 0; mf < 2; mf++)
#pragma unroll
        for (int nf = 0; nf < 8; nf++)
#pragma unroll
            for (int c = 0; c < 4; c++) acc[mf][nf][c] = 0.0f;

    // prologue: prefetch stages 0,1
    issue_copy(smb, smb + A_STAGE, A, W, ldN, m0, n0, 0, tid);
    cp_commit();
    issue_copy(smb + STAGE_BYTES, smb + STAGE_BYTES + A_STAGE, A, W, ldN, m0, n0, 1, tid);
    cp_commit();

    for (int kt = 0; kt < NKT; kt++) {
        cp_wait<STAGES - 2>();      // stage kt landed
        __syncthreads();            // all warps past mma(kt-1); smem visible

        if (kt + STAGES - 1 < NKT) {
            uint32_t st = smb + ((kt + STAGES - 1) % STAGES) * STAGE_BYTES;
            issue_copy(st, st + A_STAGE, A, W, ldN, m0, n0, kt + STAGES - 1, tid);
        }
        cp_commit();                // commit every iter -> stable group count

        const uint32_t sA = smb + (kt % STAGES) * STAGE_BYTES;
        const uint32_t sB = sA + A_STAGE;

#pragma unroll
        for (int ks = 0; ks < 4; ks++) {
            const int ga = ks * 2;          // even granule of this k-group
            uint32_t a[2][4];
#pragma unroll
            for (int mf = 0; mf < 2; mf++) {
                int rb = warp_m * 32 + mf * 16 + g8;     // rb&7 == g8
                uint32_t r0 = sA + rb * 128 + t4 * 4;
                uint32_t r1 = r0 + 8 * 128;
                uint32_t s1 = (uint32_t)((ga ^ g8) << 4);
                uint32_t s2 = (uint32_t)(((ga + 1) ^ g8) << 4);
                a[mf][0] = lds_tf32(r0 + s1);
                a[mf][1] = lds_tf32(r1 + s1);
                a[mf][2] = lds_tf32(r0 + s2);
                a[mf][3] = lds_tf32(r1 + s2);
            }
#pragma unroll
            for (int nf = 0; nf < 8; nf++) {
                int nc = warp_n * 64 + nf * 8 + g8;
                uint32_t swc = (uint32_t)((((nc >> 2) ^ (t4 << 1)) << 4) + (nc & 3) * 4);
                uint32_t b0 = lds_tf32(sB + (ks * 8 + t4) * 512 + swc);
                uint32_t b1 = lds_tf32(sB + (ks * 8 + t4 + 4) * 512 + swc);
                mma_tf32(acc[0][nf], a[0][0], a[0][1], a[0][2], a[0][3], b0, b1);
                mma_tf32(acc[1][nf], a[1][0], a[1][1], a[1][2], a[1][3], b0, b1);
            }
        }
        __syncthreads();            // done reading stage kt (reused at kt+1's issue)
    }

    // epilogue: bias + store (c0,c1 @ row, c2,c3 @ row+8), float2 each
#pragma unroll
    for (int mf = 0; mf < 2; mf++) {
        int row = m0 + warp_m * 32 + mf * 16 + g8;
#pragma unroll
        for (int nf = 0; nf < 8; nf++) {
            int col = n0 + warp_n * 64 + nf * 8 + 2 * t4;
            float b0 = bias[col], b1 = bias[col + 1];
            float2 o0 = make_float2(acc[mf][nf][0] + b0, acc[mf][nf][1] + b1);
            float2 o1 = make_float2(acc[mf][nf][2] + b0, acc[mf][nf][3] + b1);
            *(float2*)&C[(size_t)row * ldN + col] = o0;
            *(float2*)&C[(size_t)(row + 8) * ldN + col] = o1;
        }
    }
}

// ---------------- attention: one warp per (batch, head) ----------------
__global__ __launch_bounds__(256) void attn_kernel()
{
    int gwarp = blockIdx.x * 8 + (threadIdx.x >> 5);
    int lane = threadIdx.x & 31;
    if (gwarp >= BATCH * HEADS) return;
    int b = gwarp >> 3;
    int h = gwarp & 7;

    const float* qb  = g_Q  + (size_t)b * SEQ * DIM       + h * 64;
    const float* kvb = g_KV + (size_t)b * SEQ * (2 * DIM) + h * 64;

    float q0[4], q1[4], k0[4], k1[4], v0[4], v1[4];
#pragma unroll
    for (int i = 0; i < 4; i++) {
        q0[i] = qb[i * DIM + lane];
        q1[i] = qb[i * DIM + 32 + lane];
        k0[i] = kvb[i * (2 * DIM) + lane];
        k1[i] = kvb[i * (2 * DIM) + 32 + lane];
        v0[i] = kvb[i * (2 * DIM) + DIM + lane];
        v1[i] = kvb[i * (2 * DIM) + DIM + 32 + lane];
    }

    float s[4][4];
#pragma unroll
    for (int i = 0; i < 4; i++) {
#pragma unroll
        for (int j = 0; j < 4; j++) {
            float p = q0[i] * k0[j] + q1[i] * k1[j];
#pragma unroll
            for (int o = 16; o > 0; o >>= 1)
                p += __shfl_xor_sync(0xFFFFFFFFu, p, o);
            s[i][j] = p * SCALE_F;
        }
    }

#pragma unroll
    for (int i = 0; i < 4; i++) {
        int jm = 3 - i;                         // masked pair (dist = sqrt2)
        s[i][jm] = -(float)(jm + 1) * GAMMA_F;  // finite bias, stays in denominator

        float mx = fmaxf(fmaxf(s[i][0], s[i][1]), fmaxf(s[i][2], s[i][3]));
        float e[4], sum = 0.0f;
#pragma unroll
        for (int j = 0; j < 4; j++) { e[j] = expf(s[i][j] - mx); sum += e[j]; }
        float inv = 1.0f / sum;
        float p[4];
#pragma unroll
        for (int j = 0; j < 4; j++) p[j] = e[j] * inv;
        p[jm] = 0.0f;                           // post-softmax mask

        float o0 = 0.0f, o1 = 0.0f;
#pragma unroll
        for (int j = 0; j < 4; j++) { o0 += p[j] * v0[j]; o1 += p[j] * v1[j]; }

        float* dst = g_AO + (size_t)(b * SEQ + i) * DIM + h * 64;
        dst[lane] = o0;
        dst[32 + lane] = o1;
    }
}

// ---------------- launch ----------------
extern "C" void kernel_launch(void* const* d_in, const int* in_sizes, int n_in,
                              void* d_out, int out_size)
{
    const float* x   = (const float*)d_in[0];
    const float* ctx = (const float*)d_in[1];
    const float* Wq  = (const float*)d_in[2];
    const float* bq  = (const float*)d_in[3];
    const float* Wkv = (const float*)d_in[4];
    const float* bkv = (const float*)d_in[5];
    const float* Wo  = (const float*)d_in[6];
    const float* bo  = (const float*)d_in[7];
    float* out = (float*)d_out;

    cudaFuncSetAttribute(gemm_mma, cudaFuncAttributeMaxDynamicSharedMemorySize, SMEM_BYTES);

    // Q = x @ Wq + bq
    gemm_mma<<<dim3(DIM / BN, ROWS / BM), 256, SMEM_BYTES>>>(x, Wq, bq, nullptr, DIM, 0);
    // KV = ctx @ Wkv + bkv
    gemm_mma<<<dim3(2 * DIM / BN, ROWS / BM), 256, SMEM_BYTES>>>(ctx, Wkv, bkv, nullptr, 2 * DIM, 1);
    // attention
    attn_kernel<<<BATCH * HEADS / 8, 256>>>();
    // out = AO @ Wo + bo
    gemm_mma<<<dim3(DIM / BN, ROWS / BM), 256, SMEM_BYTES>>>(nullptr, Wo, bo, out, DIM, 2);
}

// round 5
// speedup vs baseline: 3.1486x; 1.1317x over previous
#include <cuda_runtime.h>
#include <cstdint>

// ---------------- problem constants ----------------
#define BATCH   16384
#define SEQ     4
#define DIM     512
#define ROWS    (BATCH * SEQ)      // 65536
#define HEADS   8
#define GAMMA_F 0.4f
#define SCALE_F 0.044194173824159216f  // 512^-0.5

// scratch (allocation-free rule)
__device__ float g_Q  [ROWS * DIM];
__device__ float g_KV [ROWS * 2 * DIM];
__device__ float g_AO [ROWS * DIM];
// pre-transposed, tf32-rounded weights: Wt[n][k]
__device__ float g_WtQ [DIM * DIM];
__device__ float g_WtKV[2 * DIM * DIM];
__device__ float g_WtO [DIM * DIM];

// ---------------- GEMM tiling ----------------
#define BM 128
#define BN 128
#define BK 32
#define NKT (DIM / BK)              // 16
#define STAGES 3
#define W_STAGE 16384               // 128 n-rows x 128B, swizzled
#define X_STAGE 16384               // 128 m-rows x 128B, swizzled
#define STAGE_BYTES (W_STAGE + X_STAGE)
#define SMEM_BYTES (STAGES * STAGE_BYTES)   // 98304 -> 2 CTA/SM

// ---------------- helpers ----------------
__device__ __forceinline__ uint32_t smem_u32(const void* p) {
    uint32_t a;
    asm("{ .reg .u64 t; cvta.to.shared.u64 t, %1; cvt.u32.u64 %0, t; }"
        : "=r"(a) : "l"(p));
    return a;
}
__device__ __forceinline__ uint32_t f2tf32(float x) {
    uint32_t u;
    asm("cvt.rna.tf32.f32 %0, %1;" : "=r"(u) : "f"(x));
    return u;
}
__device__ __forceinline__ uint32_t rnd_bits(uint32_t raw) {
    return f2tf32(__uint_as_float(raw));
}
__device__ __forceinline__ void cp16(uint32_t dst, const float* src) {
    asm volatile("cp.async.cg.shared.global [%0], [%1], 16;"
                 :: "r"(dst), "l"(src));
}
__device__ __forceinline__ void cp_commit() {
    asm volatile("cp.async.commit_group;");
}
template <int N>
__device__ __forceinline__ void cp_wait() {
    asm volatile("cp.async.wait_group %0;" :: "n"(N));
}
#define LDSM4(r0, r1, r2, r3, a) \
    asm volatile("ldmatrix.sync.aligned.m8n8.x4.shared.b16 {%0,%1,%2,%3}, [%4];" \
        : "=r"(r0), "=r"(r1), "=r"(r2), "=r"(r3) : "r"(a))

__device__ __forceinline__ void mma_tf32(
    float c[4], uint32_t a0, uint32_t a1, uint32_t a2, uint32_t a3,
    uint32_t b0, uint32_t b1)
{
    asm volatile(
        "mma.sync.aligned.m16n8k8.row.col.f32.tf32.tf32.f32 "
        "{%0,%1,%2,%3}, {%4,%5,%6,%7}, {%8,%9}, {%0,%1,%2,%3};"
        : "+f"(c[0]), "+f"(c[1]), "+f"(c[2]), "+f"(c[3])
        : "r"(a0), "r"(a1), "r"(a2), "r"(a3), "r"(b0), "r"(b1));
}

// ---------------- prep: Wt[n][k] = tf32_rna(W[k][n]) ----------------
__global__ void transpose_round(const float* __restrict__ W, int N, int sel)
{
    float* Wt = (sel == 0) ? g_WtQ : (sel == 1) ? g_WtKV : g_WtO;
    __shared__ float t[32][33];
    int k0 = blockIdx.x * 32, n0 = blockIdx.y * 32;
    int tx = threadIdx.x, ty = threadIdx.y;
#pragma unroll
    for (int i = ty; i < 32; i += 8)
        t[i][tx] = W[(size_t)(k0 + i) * N + n0 + tx];
    __syncthreads();
#pragma unroll
    for (int i = ty; i < 32; i += 8)
        Wt[(size_t)(n0 + i) * DIM + k0 + tx] =
            __uint_as_float(f2tf32(t[tx][i]));
}

// cp.async one k-tile: Wt tile -> sW, Act tile -> sX (both [row][8 x 16B granules])
__device__ __forceinline__ void issue_copy(
    uint32_t sW, uint32_t sX,
    const float* __restrict__ Wt, const float* __restrict__ Act,
    int m0, int n0, int t, int tid)
{
#pragma unroll
    for (int j = 0; j < 4; j++) {
        int g = tid + j * 256;
        int r = g >> 3, c = g & 7;
        uint32_t off = (uint32_t)(r * 128 + ((c ^ (r & 7)) << 4));
        cp16(sW + off, &Wt[(size_t)(n0 + r) * DIM + t * BK + c * 4]);
        cp16(sX + off, &Act[(size_t)(m0 + r) * DIM + t * BK + c * 4]);
    }
}

// ---------------- tf32 GEMM: C[m][n] = Act[m][512] @ W[512][n] + bias ----------------
// mma operands swapped: A = Wt (pre-rounded, no cvt), B = Act (ldmatrix + cvt).
__global__ __launch_bounds__(256, 2) void gemm_mma(
    const float* __restrict__ ActExt,
    const float* __restrict__ bias, float* __restrict__ Cext,
    int ldN, int mode)
{
    extern __shared__ float smf[];
    const uint32_t smb = smem_u32(smf);

    const float* Act = (mode == 2) ? g_AO : ActExt;
    const float* Wt  = (mode == 0) ? g_WtQ : (mode == 1) ? g_WtKV : g_WtO;
    float* C = (mode == 0) ? g_Q : (mode == 1) ? g_KV : Cext;

    const int tid = threadIdx.x;
    const int wid = tid >> 5;
    const int l   = tid & 31;
    const int wn = wid & 3;         // n-quadrant (32 each)
    const int wm = wid >> 2;        // m-half (64 each)
    const int nb = wn * 32, mb = wm * 64;
    const int m0 = blockIdx.y * BM, n0 = blockIdx.x * BN;

    // lane-derived ldmatrix row constants (all row bases are multiples of 8,
    // so row&7 == l&7 for every matrix -> swizzle xor value is lane-constant)
    const int lx7  = l & 7;
    const int lrow = (l & 7) + ((l >> 3) & 1) * 8;  // Wt matrices: row-in-frag
    const int lhi  = l >> 4;                        // Wt: granule offset
    const int xrow = ((l >> 4) << 3) + (l & 7);     // Act matrices: row-in-frag
    const int xgb  = (l >> 3) & 1;                  // Act: granule offset

    float acc[2][8][4];
#pragma unroll
    for (int i = 0; i < 2; i++)
#pragma unroll
        for (int j = 0; j < 8; j++)
#pragma unroll
            for (int c = 0; c < 4; c++) acc[i][j][c] = 0.0f;

    // prologue: prefetch stages 0,1
    issue_copy(smb, smb + W_STAGE, Wt, Act, m0, n0, 0, tid);
    cp_commit();
    issue_copy(smb + STAGE_BYTES, smb + STAGE_BYTES + W_STAGE, Wt, Act, m0, n0, 1, tid);
    cp_commit();

    for (int kt = 0; kt < NKT; kt++) {
        cp_wait<STAGES - 2>();
        __syncthreads();

        if (kt + STAGES - 1 < NKT) {
            uint32_t st = smb + ((kt + STAGES - 1) % STAGES) * STAGE_BYTES;
            issue_copy(st, st + W_STAGE, Wt, Act, m0, n0, kt + STAGES - 1, tid);
        }
        cp_commit();

        const uint32_t sW = smb + (kt % STAGES) * STAGE_BYTES;
        const uint32_t sX = sW + W_STAGE;

#pragma unroll
        for (int ks = 0; ks < 4; ks++) {
            // A fragments (Wt, pre-rounded -> no cvt)
            uint32_t aw[2][4];
#pragma unroll
            for (int inf = 0; inf < 2; inf++) {
                int row = nb + inf * 16 + lrow;
                uint32_t ad = sW + row * 128 + (uint32_t)(((2 * ks + lhi) ^ lx7) << 4);
                LDSM4(aw[inf][0], aw[inf][1], aw[inf][2], aw[inf][3], ad);
            }
            // B fragments (Act) + rna rounding
            uint32_t bx[8][2];
#pragma unroll
            for (int jp = 0; jp < 4; jp++) {
                int row = mb + jp * 16 + xrow;
                uint32_t ad = sX + row * 128 + (uint32_t)(((2 * ks + xgb) ^ lx7) << 4);
                uint32_t r0, r1, r2, r3;
                LDSM4(r0, r1, r2, r3, ad);
                bx[2 * jp][0]     = rnd_bits(r0);
                bx[2 * jp][1]     = rnd_bits(r1);
                bx[2 * jp + 1][0] = rnd_bits(r2);
                bx[2 * jp + 1][1] = rnd_bits(r3);
            }
#pragma unroll
            for (int inf = 0; inf < 2; inf++)
#pragma unroll
                for (int jm = 0; jm < 8; jm++)
                    mma_tf32(acc[inf][jm],
                             aw[inf][0], aw[inf][1], aw[inf][2], aw[inf][3],
                             bx[jm][0], bx[jm][1]);
        }
        __syncthreads();
    }

    // ---------------- epilogue: transpose via smem, bias, coalesced store ----
    cp_wait<0>();
    __syncthreads();
    float* Cs = smf;                 // [128 m][132 pitch] fp32 = 67.6KB
    const int gq = l >> 2, tq = l & 3;
#pragma unroll
    for (int inf = 0; inf < 2; inf++) {
        int nn = nb + inf * 16 + gq;
#pragma unroll
        for (int jm = 0; jm < 8; jm++) {
            int mm = mb + jm * 8 + 2 * tq;
            Cs[mm * 132 + nn]           = acc[inf][jm][0];
            Cs[(mm + 1) * 132 + nn]     = acc[inf][jm][1];
            Cs[mm * 132 + nn + 8]       = acc[inf][jm][2];
            Cs[(mm + 1) * 132 + nn + 8] = acc[inf][jm][3];
        }
    }
    __syncthreads();
#pragma unroll
    for (int it = 0; it < 16; it++) {
        int idx = tid + it * 256;
        int r = idx >> 5, c = (idx & 31) * 4;
        float4 v = *(float4*)&Cs[r * 132 + c];
        v.x += bias[n0 + c];
        v.y += bias[n0 + c + 1];
        v.z += bias[n0 + c + 2];
        v.w += bias[n0 + c + 3];
        *(float4*)&C[(size_t)(m0 + r) * ldN + n0 + c] = v;
    }
}

// ---------------- attention: one warp per (batch, head) ----------------
__global__ __launch_bounds__(256) void attn_kernel()
{
    int gwarp = blockIdx.x * 8 + (threadIdx.x >> 5);
    int lane = threadIdx.x & 31;
    if (gwarp >= BATCH * HEADS) return;
    int b = gwarp >> 3;
    int h = gwarp & 7;

    const float* qb  = g_Q  + (size_t)b * SEQ * DIM       + h * 64;
    const float* kvb = g_KV + (size_t)b * SEQ * (2 * DIM) + h * 64;

    float q0[4], q1[4], k0[4], k1[4], v0[4], v1[4];
#pragma unroll
    for (int i = 0; i < 4; i++) {
        q0[i] = qb[i * DIM + lane];
        q1[i] = qb[i * DIM + 32 + lane];
        k0[i] = kvb[i * (2 * DIM) + lane];
        k1[i] = kvb[i * (2 * DIM) + 32 + lane];
        v0[i] = kvb[i * (2 * DIM) + DIM + lane];
        v1[i] = kvb[i * (2 * DIM) + DIM + 32 + lane];
    }

    float s[4][4];
#pragma unroll
    for (int i = 0; i < 4; i++) {
#pragma unroll
        for (int j = 0; j < 4; j++) {
            float p = q0[i] * k0[j] + q1[i] * k1[j];
#pragma unroll
            for (int o = 16; o > 0; o >>= 1)
                p += __shfl_xor_sync(0xFFFFFFFFu, p, o);
            s[i][j] = p * SCALE_F;
        }
    }

#pragma unroll
    for (int i = 0; i < 4; i++) {
        int jm = 3 - i;                         // masked pair (dist = sqrt2)
        s[i][jm] = -(float)(jm + 1) * GAMMA_F;  // finite bias, stays in denominator

        float mx = fmaxf(fmaxf(s[i][0], s[i][1]), fmaxf(s[i][2], s[i][3]));
        float e[4], sum = 0.0f;
#pragma unroll
        for (int j = 0; j < 4; j++) { e[j] = expf(s[i][j] - mx); sum += e[j]; }
        float inv = 1.0f / sum;
        float p[4];
#pragma unroll
        for (int j = 0; j < 4; j++) p[j] = e[j] * inv;
        p[jm] = 0.0f;                           // post-softmax mask

        float o0 = 0.0f, o1 = 0.0f;
#pragma unroll
        for (int j = 0; j < 4; j++) { o0 += p[j] * v0[j]; o1 += p[j] * v1[j]; }

        float* dst = g_AO + (size_t)(b * SEQ + i) * DIM + h * 64;
        dst[lane] = o0;
        dst[32 + lane] = o1;
    }
}

// ---------------- launch ----------------
extern "C" void kernel_launch(void* const* d_in, const int* in_sizes, int n_in,
                              void* d_out, int out_size)
{
    const float* x   = (const float*)d_in[0];
    const float* ctx = (const float*)d_in[1];
    const float* Wq  = (const float*)d_in[2];
    const float* bq  = (const float*)d_in[3];
    const float* Wkv = (const float*)d_in[4];
    const float* bkv = (const float*)d_in[5];
    const float* Wo  = (const float*)d_in[6];
    const float* bo  = (const float*)d_in[7];
    float* out = (float*)d_out;

    cudaFuncSetAttribute(gemm_mma, cudaFuncAttributeMaxDynamicSharedMemorySize, SMEM_BYTES);

    // prep: transpose + tf32-round weights (tiny)
    dim3 tb(32, 8);
    transpose_round<<<dim3(DIM / 32, DIM / 32), tb>>>(Wq, DIM, 0);
    transpose_round<<<dim3(DIM / 32, 2 * DIM / 32), tb>>>(Wkv, 2 * DIM, 1);
    transpose_round<<<dim3(DIM / 32, DIM / 32), tb>>>(Wo, DIM, 2);

    // Q = x @ Wq + bq
    gemm_mma<<<dim3(DIM / BN, ROWS / BM), 256, SMEM_BYTES>>>(x, bq, nullptr, DIM, 0);
    // KV = ctx @ Wkv + bkv
    gemm_mma<<<dim3(2 * DIM / BN, ROWS / BM), 256, SMEM_BYTES>>>(ctx, bkv, nullptr, 2 * DIM, 1);
    // attention
    attn_kernel<<<BATCH * HEADS / 8, 256>>>();
    // out = AO @ Wo + bo
    gemm_mma<<<dim3(DIM / BN, ROWS / BM), 256, SMEM_BYTES>>>(nullptr, bo, out, DIM, 2);
}

// round 7
// speedup vs baseline: 4.9410x; 1.5693x over previous
#include <cuda_runtime.h>
#include <cuda_fp16.h>
#include <cstdint>

// ---------------- problem constants ----------------
#define BATCH   16384
#define SEQ     4
#define DIM     512
#define ROWS    (BATCH * SEQ)      // 65536
#define HEADS   8
#define GAMMA_F 0.4f
#define SCALE_F 0.044194173824159216f  // 512^-0.5

// scratch (allocation-free rule)
__device__ float  g_Q  [ROWS * DIM];          // fp32 (attention input)
__device__ float  g_KV [ROWS * 2 * DIM];      // fp32 (attention input)
__device__ __half g_AOh[ROWS * DIM];          // fp16 (mode-2 GEMM operand)
__device__ __half g_Xh [ROWS * DIM];          // fp16 x
__device__ __half g_Ch [ROWS * DIM];          // fp16 context
// pre-transposed fp16 weights: Wt[n][k]
__device__ __half g_WtQh [DIM * DIM];
__device__ __half g_WtKVh[2 * DIM * DIM];
__device__ __half g_WtOh [DIM * DIM];

// ---------------- GEMM tiling ----------------
#define BM 128
#define BN 128
#define BK 64                       // 64 fp16 = 128B rows
#define NKT (DIM / BK)              // 8
#define STAGES 3
#define W_STAGE 16384               // 128 n-rows x 128B, swizzled
#define X_STAGE 16384               // 128 m-rows x 128B, swizzled
#define STAGE_BYTES (W_STAGE + X_STAGE)
#define SMEM_BYTES (STAGES * STAGE_BYTES)   // 98304 -> 2 CTA/SM

// ---------------- helpers ----------------
__device__ __forceinline__ uint32_t smem_u32(const void* p) {
    uint32_t a;
    asm("{ .reg .u64 t; cvta.to.shared.u64 t, %1; cvt.u32.u64 %0, t; }"
        : "=r"(a) : "l"(p));
    return a;
}
__device__ __forceinline__ void cp16(uint32_t dst, const void* src) {
    asm volatile("cp.async.cg.shared.global [%0], [%1], 16;"
                 :: "r"(dst), "l"(src));
}
__device__ __forceinline__ void cp_commit() {
    asm volatile("cp.async.commit_group;");
}
template <int N>
__device__ __forceinline__ void cp_wait() {
    asm volatile("cp.async.wait_group %0;" :: "n"(N));
}
#define LDSM4(r0, r1, r2, r3, a) \
    asm volatile("ldmatrix.sync.aligned.m8n8.x4.shared.b16 {%0,%1,%2,%3}, [%4];" \
        : "=r"(r0), "=r"(r1), "=r"(r2), "=r"(r3) : "r"(a))

__device__ __forceinline__ void mma_f16(
    float c[4], uint32_t a0, uint32_t a1, uint32_t a2, uint32_t a3,
    uint32_t b0, uint32_t b1)
{
    asm volatile(
        "mma.sync.aligned.m16n8k16.row.col.f32.f16.f16.f32 "
        "{%0,%1,%2,%3}, {%4,%5,%6,%7}, {%8,%9}, {%0,%1,%2,%3};"
        : "+f"(c[0]), "+f"(c[1]), "+f"(c[2]), "+f"(c[3])
        : "r"(a0), "r"(a1), "r"(a2), "r"(a3), "r"(b0), "r"(b1));
}

// ---------------- prep: Wt[n][k] = fp16(W[k][n]) ----------------
__global__ void transpose_half(const float* __restrict__ W, int N, int sel)
{
    __half* Wt = (sel == 0) ? g_WtQh : (sel == 1) ? g_WtKVh : g_WtOh;
    __shared__ float t[32][33];
    int k0 = blockIdx.x * 32, n0 = blockIdx.y * 32;
    int tx = threadIdx.x, ty = threadIdx.y;
#pragma unroll
    for (int i = ty; i < 32; i += 8)
        t[i][tx] = W[(size_t)(k0 + i) * N + n0 + tx];
    __syncthreads();
#pragma unroll
    for (int i = ty; i < 32; i += 8)
        Wt[(size_t)(n0 + i) * DIM + k0 + tx] = __float2half_rn(t[tx][i]);
}

// ---------------- prep: fp32 -> fp16 (dst selected ON DEVICE) ----------------
__global__ void to_half(const float* __restrict__ src, int sel)
{
    __half* dst = (sel == 0) ? g_Xh : g_Ch;
    int i = (blockIdx.x * blockDim.x + threadIdx.x) * 4;
    float4 v = *(const float4*)&src[i];
    *(__half2*)&dst[i]     = __floats2half2_rn(v.x, v.y);
    *(__half2*)&dst[i + 2] = __floats2half2_rn(v.z, v.w);
}

// cp.async one k-tile: Wt tile -> sW, Act tile -> sX. rows of 64 fp16 (8x16B granules)
__device__ __forceinline__ void issue_copy(
    uint32_t sW, uint32_t sX,
    const __half* __restrict__ Wt, const __half* __restrict__ Act,
    int m0, int n0, int t, int tid)
{
#pragma unroll
    for (int j = 0; j < 4; j++) {
        int g = tid + j * 256;
        int r = g >> 3, c = g & 7;
        uint32_t off = (uint32_t)(r * 128 + ((c ^ (r & 7)) << 4));
        cp16(sW + off, &Wt[(size_t)(n0 + r) * DIM + t * BK + c * 8]);
        cp16(sX + off, &Act[(size_t)(m0 + r) * DIM + t * BK + c * 8]);
    }
}

// ---------------- fp16 GEMM: C[m][n] = Act[m][512] @ W[512][n] + bias ----------------
// mma operands swapped: A = Wt[n][k], B = Act[m][k]; fp16 in, fp32 accum.
__global__ __launch_bounds__(256, 2) void gemm_mma(
    const float* __restrict__ bias, float* __restrict__ Cext,
    int ldN, int mode)
{
    extern __shared__ float smf[];
    const uint32_t smb = smem_u32(smf);

    const __half* Act = (mode == 0) ? g_Xh : (mode == 1) ? g_Ch : g_AOh;
    const __half* Wt  = (mode == 0) ? g_WtQh : (mode == 1) ? g_WtKVh : g_WtOh;
    float* C = (mode == 0) ? g_Q : (mode == 1) ? g_KV : Cext;

    const int tid = threadIdx.x;
    const int wid = tid >> 5;
    const int l   = tid & 31;
    const int wn = wid & 3;         // n-quadrant (32 each)
    const int wm = wid >> 2;        // m-half (64 each)
    const int nb = wn * 32, mb = wm * 64;
    const int m0 = blockIdx.y * BM, n0 = blockIdx.x * BN;

    // ldmatrix lane constants (row bases are multiples of 8 -> row&7 == l&7)
    const int lx7  = l & 7;
    const int arow = (l & 7) + ((l >> 3) & 1) * 8;   // Wt frag row offset
    const int agb  = l >> 4;                          // Wt granule offset
    const int brow = (l & 7) + ((l >> 4) << 3);       // Act frag row offset
    const int bgb  = (l >> 3) & 1;                    // Act granule offset

    float acc[2][8][4];
#pragma unroll
    for (int i = 0; i < 2; i++)
#pragma unroll
        for (int j = 0; j < 8; j++)
#pragma unroll
            for (int c = 0; c < 4; c++) acc[i][j][c] = 0.0f;

    // prologue: prefetch stages 0,1
    issue_copy(smb, smb + W_STAGE, Wt, Act, m0, n0, 0, tid);
    cp_commit();
    issue_copy(smb + STAGE_BYTES, smb + STAGE_BYTES + W_STAGE, Wt, Act, m0, n0, 1, tid);
    cp_commit();

    for (int kt = 0; kt < NKT; kt++) {
        cp_wait<STAGES - 2>();
        __syncthreads();

        if (kt + STAGES - 1 < NKT) {
            uint32_t st = smb + ((kt + STAGES - 1) % STAGES) * STAGE_BYTES;
            issue_copy(st, st + W_STAGE, Wt, Act, m0, n0, kt + STAGES - 1, tid);
        }
        cp_commit();

        const uint32_t sW = smb + (kt % STAGES) * STAGE_BYTES;
        const uint32_t sX = sW + W_STAGE;

#pragma unroll
        for (int ks = 0; ks < 4; ks++) {           // k16 per step, 4 steps = BK
            // A fragments (Wt): 2 n-frags of 16
            uint32_t aw[2][4];
#pragma unroll
            for (int inf = 0; inf < 2; inf++) {
                int row = nb + inf * 16 + arow;
                uint32_t ad = sW + row * 128
                            + (uint32_t)(((2 * ks + agb) ^ lx7) << 4);
                LDSM4(aw[inf][0], aw[inf][1], aw[inf][2], aw[inf][3], ad);
            }
            // B fragments (Act): 8 m-frags of 8 (2 per LDSM4)
            uint32_t bx[8][2];
#pragma unroll
            for (int jp = 0; jp < 4; jp++) {
                int row = mb + jp * 16 + brow;
                uint32_t ad = sX + row * 128
                            + (uint32_t)(((2 * ks + bgb) ^ lx7) << 4);
                uint32_t r0, r1, r2, r3;
                LDSM4(r0, r1, r2, r3, ad);
                bx[2 * jp][0]     = r0;  // rows 0-7,  k 0-7
                bx[2 * jp][1]     = r1;  // rows 0-7,  k 8-15
                bx[2 * jp + 1][0] = r2;  // rows 8-15, k 0-7
                bx[2 * jp + 1][1] = r3;  // rows 8-15, k 8-15
            }
#pragma unroll
            for (int inf = 0; inf < 2; inf++)
#pragma unroll
                for (int jm = 0; jm < 8; jm++)
                    mma_f16(acc[inf][jm],
                            aw[inf][0], aw[inf][1], aw[inf][2], aw[inf][3],
                            bx[jm][0], bx[jm][1]);
        }
        __syncthreads();
    }

    // ---------------- epilogue: transpose via smem, bias, coalesced store ----
    cp_wait<0>();
    __syncthreads();
    float* Cs = smf;                 // [128 m][132 pitch] fp32
    const int gq = l >> 2, tq = l & 3;
#pragma unroll
    for (int inf = 0; inf < 2; inf++) {
        int nn = nb + inf * 16 + gq;
#pragma unroll
        for (int jm = 0; jm < 8; jm++) {
            int mm = mb + jm * 8 + 2 * tq;
            Cs[mm * 132 + nn]           = acc[inf][jm][0];
            Cs[(mm + 1) * 132 + nn]     = acc[inf][jm][1];
            Cs[mm * 132 + nn + 8]       = acc[inf][jm][2];
            Cs[(mm + 1) * 132 + nn + 8] = acc[inf][jm][3];
        }
    }
    __syncthreads();
#pragma unroll
    for (int it = 0; it < 16; it++) {
        int idx = tid + it * 256;
        int r = idx >> 5, c = (idx & 31) * 4;
        float4 v = *(float4*)&Cs[r * 132 + c];
        v.x += bias[n0 + c];
        v.y += bias[n0 + c + 1];
        v.z += bias[n0 + c + 2];
        v.w += bias[n0 + c + 3];
        *(float4*)&C[(size_t)(m0 + r) * ldN + n0 + c] = v;
    }
}

// ---------------- attention: one warp per (batch, head), fp16 output ----------------
__global__ __launch_bounds__(256) void attn_kernel()
{
    int gwarp = blockIdx.x * 8 + (threadIdx.x >> 5);
    int lane = threadIdx.x & 31;
    if (gwarp >= BATCH * HEADS) return;
    int b = gwarp >> 3;
    int h = gwarp & 7;

    const float* qb  = g_Q  + (size_t)b * SEQ * DIM       + h * 64;
    const float* kvb = g_KV + (size_t)b * SEQ * (2 * DIM) + h * 64;

    float q0[4], q1[4], k0[4], k1[4], v0[4], v1[4];
#pragma unroll
    for (int i = 0; i < 4; i++) {
        q0[i] = qb[i * DIM + lane];
        q1[i] = qb[i * DIM + 32 + lane];
        k0[i] = kvb[i * (2 * DIM) + lane];
        k1[i] = kvb[i * (2 * DIM) + 32 + lane];
        v0[i] = kvb[i * (2 * DIM) + DIM + lane];
        v1[i] = kvb[i * (2 * DIM) + DIM + 32 + lane];
    }

    float s[4][4];
#pragma unroll
    for (int i = 0; i < 4; i++) {
#pragma unroll
        for (int j = 0; j < 4; j++) {
            float p = q0[i] * k0[j] + q1[i] * k1[j];
#pragma unroll
            for (int o = 16; o > 0; o >>= 1)
                p += __shfl_xor_sync(0xFFFFFFFFu, p, o);
            s[i][j] = p * SCALE_F;
        }
    }

#pragma unroll
    for (int i = 0; i < 4; i++) {
        int jm = 3 - i;                         // masked pair (dist = sqrt2)
        s[i][jm] = -(float)(jm + 1) * GAMMA_F;  // finite bias, stays in denominator

        float mx = fmaxf(fmaxf(s[i][0], s[i][1]), fmaxf(s[i][2], s[i][3]));
        float e[4], sum = 0.0f;
#pragma unroll
        for (int j = 0; j < 4; j++) { e[j] = expf(s[i][j] - mx); sum += e[j]; }
        float inv = 1.0f / sum;
        float p[4];
#pragma unroll
        for (int j = 0; j < 4; j++) p[j] = e[j] * inv;
        p[jm] = 0.0f;                           // post-softmax mask

        float o0 = 0.0f, o1 = 0.0f;
#pragma unroll
        for (int j = 0; j < 4; j++) { o0 += p[j] * v0[j]; o1 += p[j] * v1[j]; }

        __half* dst = g_AOh + (size_t)(b * SEQ + i) * DIM + h * 64;
        dst[lane]      = __float2half_rn(o0);
        dst[32 + lane] = __float2half_rn(o1);
    }
}

// ---------------- launch ----------------
extern "C" void kernel_launch(void* const* d_in, const int* in_sizes, int n_in,
                              void* d_out, int out_size)
{
    const float* x   = (const float*)d_in[0];
    const float* ctx = (const float*)d_in[1];
    const float* Wq  = (const float*)d_in[2];
    const float* bq  = (const float*)d_in[3];
    const float* Wkv = (const float*)d_in[4];
    const float* bkv = (const float*)d_in[5];
    const float* Wo  = (const float*)d_in[6];
    const float* bo  = (const float*)d_in[7];
    float* out = (float*)d_out;

    cudaFuncSetAttribute(gemm_mma, cudaFuncAttributeMaxDynamicSharedMemorySize, SMEM_BYTES);

    // prep: weights -> fp16 transposed; activations -> fp16 (dst chosen on device)
    dim3 tb(32, 8);
    transpose_half<<<dim3(DIM / 32, DIM / 32), tb>>>(Wq, DIM, 0);
    transpose_half<<<dim3(DIM / 32, 2 * DIM / 32), tb>>>(Wkv, 2 * DIM, 1);
    transpose_half<<<dim3(DIM / 32, DIM / 32), tb>>>(Wo, DIM, 2);
    to_half<<<(ROWS * DIM / 4) / 256, 256>>>(x, 0);
    to_half<<<(ROWS * DIM / 4) / 256, 256>>>(ctx, 1);

    // Q = x @ Wq + bq (fp32 out)
    gemm_mma<<<dim3(DIM / BN, ROWS / BM), 256, SMEM_BYTES>>>(bq, nullptr, DIM, 0);
    // KV = ctx @ Wkv + bkv (fp32 out)
    gemm_mma<<<dim3(2 * DIM / BN, ROWS / BM), 256, SMEM_BYTES>>>(bkv, nullptr, 2 * DIM, 1);
    // attention (writes fp16 AO)
    attn_kernel<<<BATCH * HEADS / 8, 256>>>();
    // out = AO @ Wo + bo
    gemm_mma<<<dim3(DIM / BN, ROWS / BM), 256, SMEM_BYTES>>>(bo, out, DIM, 2);
}

// round 8
// speedup vs baseline: 5.1005x; 1.0323x over previous
#include <cuda_runtime.h>
#include <cuda_fp16.h>
#include <cstdint>

// ---------------- problem constants ----------------
#define BATCH   16384
#define SEQ     4
#define DIM     512
#define ROWS    (BATCH * SEQ)      // 65536
#define HEADS   8
#define GAMMA_F 0.4f
#define SCALE_F 0.044194173824159216f  // 512^-0.5

// scratch (allocation-free rule)
__device__ __half g_Qh [ROWS * DIM];          // fp16 Q (attention input)
__device__ __half g_KVh[ROWS * 2 * DIM];      // fp16 KV (attention input)
__device__ __half g_AOh[ROWS * DIM];          // fp16 attention output
__device__ __half g_Xh [ROWS * DIM];          // fp16 x
__device__ __half g_Ch [ROWS * DIM];          // fp16 context
// pre-transposed fp16 weights: Wt[n][k]
__device__ __half g_WtQh [DIM * DIM];
__device__ __half g_WtKVh[2 * DIM * DIM];
__device__ __half g_WtOh [DIM * DIM];

// ---------------- GEMM tiling ----------------
#define BM 128
#define BN 128
#define BK 64                       // 64 fp16 = 128B rows
#define NKT (DIM / BK)              // 8
#define STAGES 3
#define W_STAGE 16384
#define X_STAGE 16384
#define STAGE_BYTES (W_STAGE + X_STAGE)
#define SMEM_BYTES (STAGES * STAGE_BYTES)   // 98304 -> 2 CTA/SM

// ---------------- helpers ----------------
__device__ __forceinline__ uint32_t smem_u32(const void* p) {
    uint32_t a;
    asm("{ .reg .u64 t; cvta.to.shared.u64 t, %1; cvt.u32.u64 %0, t; }"
        : "=r"(a) : "l"(p));
    return a;
}
__device__ __forceinline__ void cp16(uint32_t dst, const void* src) {
    asm volatile("cp.async.cg.shared.global [%0], [%1], 16;"
                 :: "r"(dst), "l"(src));
}
__device__ __forceinline__ void cp_commit() {
    asm volatile("cp.async.commit_group;");
}
template <int N>
__device__ __forceinline__ void cp_wait() {
    asm volatile("cp.async.wait_group %0;" :: "n"(N));
}
#define LDSM4(r0, r1, r2, r3, a) \
    asm volatile("ldmatrix.sync.aligned.m8n8.x4.shared.b16 {%0,%1,%2,%3}, [%4];" \
        : "=r"(r0), "=r"(r1), "=r"(r2), "=r"(r3) : "r"(a))

__device__ __forceinline__ void mma_f16(
    float c[4], uint32_t a0, uint32_t a1, uint32_t a2, uint32_t a3,
    uint32_t b0, uint32_t b1)
{
    asm volatile(
        "mma.sync.aligned.m16n8k16.row.col.f32.f16.f16.f32 "
        "{%0,%1,%2,%3}, {%4,%5,%6,%7}, {%8,%9}, {%0,%1,%2,%3};"
        : "+f"(c[0]), "+f"(c[1]), "+f"(c[2]), "+f"(c[3])
        : "r"(a0), "r"(a1), "r"(a2), "r"(a3), "r"(b0), "r"(b1));
}

// ---------------- prep: Wt[n][k] = fp16(W[k][n]) ----------------
__global__ void transpose_half(const float* __restrict__ W, int N, int sel)
{
    __half* Wt = (sel == 0) ? g_WtQh : (sel == 1) ? g_WtKVh : g_WtOh;
    __shared__ float t[32][33];
    int k0 = blockIdx.x * 32, n0 = blockIdx.y * 32;
    int tx = threadIdx.x, ty = threadIdx.y;
#pragma unroll
    for (int i = ty; i < 32; i += 8)
        t[i][tx] = W[(size_t)(k0 + i) * N + n0 + tx];
    __syncthreads();
#pragma unroll
    for (int i = ty; i < 32; i += 8)
        Wt[(size_t)(n0 + i) * DIM + k0 + tx] = __float2half_rn(t[tx][i]);
}

// ---------------- prep: fp32 -> fp16 (dst selected ON DEVICE) ----------------
__global__ void to_half(const float* __restrict__ src, int sel)
{
    __half* dst = (sel == 0) ? g_Xh : g_Ch;
    int i = (blockIdx.x * blockDim.x + threadIdx.x) * 4;
    float4 v = *(const float4*)&src[i];
    *(__half2*)&dst[i]     = __floats2half2_rn(v.x, v.y);
    *(__half2*)&dst[i + 2] = __floats2half2_rn(v.z, v.w);
}

// cp.async one k-tile: Wt tile -> sW, Act tile -> sX
__device__ __forceinline__ void issue_copy(
    uint32_t sW, uint32_t sX,
    const __half* __restrict__ Wt, const __half* __restrict__ Act,
    int m0, int n0, int t, int tid)
{
#pragma unroll
    for (int j = 0; j < 4; j++) {
        int g = tid + j * 256;
        int r = g >> 3, c = g & 7;
        uint32_t off = (uint32_t)(r * 128 + ((c ^ (r & 7)) << 4));
        cp16(sW + off, &Wt[(size_t)(n0 + r) * DIM + t * BK + c * 8]);
        cp16(sX + off, &Act[(size_t)(m0 + r) * DIM + t * BK + c * 8]);
    }
}

// ---------------- fp16 GEMM: C[m][n] = Act[m][512] @ W[512][n] + bias ----------------
// A = Wt[n][k], B = Act[m][k]; fp16 in, fp32 accum.
// mode 0 -> g_Qh (fp16), mode 1 -> g_KVh (fp16), mode 2 -> Cext (fp32)
__global__ __launch_bounds__(256, 2) void gemm_mma(
    const float* __restrict__ bias, float* __restrict__ Cext,
    int ldN, int mode)
{
    extern __shared__ float smf[];
    const uint32_t smb = smem_u32(smf);

    const __half* Act = (mode == 0) ? g_Xh : (mode == 1) ? g_Ch : g_AOh;
    const __half* Wt  = (mode == 0) ? g_WtQh : (mode == 1) ? g_WtKVh : g_WtOh;

    const int tid = threadIdx.x;
    const int wid = tid >> 5;
    const int l   = tid & 31;
    const int wn = wid & 3;
    const int wm = wid >> 2;
    const int nb = wn * 32, mb = wm * 64;
    const int m0 = blockIdx.y * BM, n0 = blockIdx.x * BN;

    const int lx7  = l & 7;
    const int arow = (l & 7) + ((l >> 3) & 1) * 8;
    const int agb  = l >> 4;
    const int brow = (l & 7) + ((l >> 4) << 3);
    const int bgb  = (l >> 3) & 1;

    float acc[2][8][4];
#pragma unroll
    for (int i = 0; i < 2; i++)
#pragma unroll
        for (int j = 0; j < 8; j++)
#pragma unroll
            for (int c = 0; c < 4; c++) acc[i][j][c] = 0.0f;

    issue_copy(smb, smb + W_STAGE, Wt, Act, m0, n0, 0, tid);
    cp_commit();
    issue_copy(smb + STAGE_BYTES, smb + STAGE_BYTES + W_STAGE, Wt, Act, m0, n0, 1, tid);
    cp_commit();

    for (int kt = 0; kt < NKT; kt++) {
        cp_wait<STAGES - 2>();
        __syncthreads();   // single barrier per k-tile (see invariant note)

        if (kt + STAGES - 1 < NKT) {
            uint32_t st = smb + ((kt + STAGES - 1) % STAGES) * STAGE_BYTES;
            issue_copy(st, st + W_STAGE, Wt, Act, m0, n0, kt + STAGES - 1, tid);
        }
        cp_commit();

        const uint32_t sW = smb + (kt % STAGES) * STAGE_BYTES;
        const uint32_t sX = sW + W_STAGE;

#pragma unroll
        for (int ks = 0; ks < 4; ks++) {
            uint32_t aw[2][4];
#pragma unroll
            for (int inf = 0; inf < 2; inf++) {
                int row = nb + inf * 16 + arow;
                uint32_t ad = sW + row * 128
                            + (uint32_t)(((2 * ks + agb) ^ lx7) << 4);
                LDSM4(aw[inf][0], aw[inf][1], aw[inf][2], aw[inf][3], ad);
            }
            uint32_t bx[8][2];
#pragma unroll
            for (int jp = 0; jp < 4; jp++) {
                int row = mb + jp * 16 + brow;
                uint32_t ad = sX + row * 128
                            + (uint32_t)(((2 * ks + bgb) ^ lx7) << 4);
                uint32_t r0, r1, r2, r3;
                LDSM4(r0, r1, r2, r3, ad);
                bx[2 * jp][0]     = r0;
                bx[2 * jp][1]     = r1;
                bx[2 * jp + 1][0] = r2;
                bx[2 * jp + 1][1] = r3;
            }
#pragma unroll
            for (int inf = 0; inf < 2; inf++)
#pragma unroll
                for (int jm = 0; jm < 8; jm++)
                    mma_f16(acc[inf][jm],
                            aw[inf][0], aw[inf][1], aw[inf][2], aw[inf][3],
                            bx[jm][0], bx[jm][1]);
        }
    }

    // ---------------- epilogue: transpose via smem, bias, coalesced store ----
    cp_wait<0>();
    __syncthreads();
    float* Cs = smf;                 // [128 m][132 pitch] fp32
    const int gq = l >> 2, tq = l & 3;
#pragma unroll
    for (int inf = 0; inf < 2; inf++) {
        int nn = nb + inf * 16 + gq;
#pragma unroll
        for (int jm = 0; jm < 8; jm++) {
            int mm = mb + jm * 8 + 2 * tq;
            Cs[mm * 132 + nn]           = acc[inf][jm][0];
            Cs[(mm + 1) * 132 + nn]     = acc[inf][jm][1];
            Cs[mm * 132 + nn + 8]       = acc[inf][jm][2];
            Cs[(mm + 1) * 132 + nn + 8] = acc[inf][jm][3];
        }
    }
    __syncthreads();

    if (mode < 2) {
        // fp16 output (Q or KV), 16B stores of 8 halves
        __half* Co = (mode == 0) ? g_Qh : g_KVh;
#pragma unroll
        for (int it = 0; it < 8; it++) {
            int idx = tid + it * 256;
            int r = idx >> 4, c = (idx & 15) * 8;
            float4 v0 = *(float4*)&Cs[r * 132 + c];
            float4 v1 = *(float4*)&Cs[r * 132 + c + 4];
            const float* bp = &bias[n0 + c];
            __half2 h[4];
            h[0] = __floats2half2_rn(v0.x + bp[0], v0.y + bp[1]);
            h[1] = __floats2half2_rn(v0.z + bp[2], v0.w + bp[3]);
            h[2] = __floats2half2_rn(v1.x + bp[4], v1.y + bp[5]);
            h[3] = __floats2half2_rn(v1.z + bp[6], v1.w + bp[7]);
            *(uint4*)&Co[(size_t)(m0 + r) * ldN + n0 + c] = *(uint4*)h;
        }
    } else {
        // fp32 output (final)
#pragma unroll
        for (int it = 0; it < 16; it++) {
            int idx = tid + it * 256;
            int r = idx >> 5, c = (idx & 31) * 4;
            float4 v = *(float4*)&Cs[r * 132 + c];
            v.x += bias[n0 + c];
            v.y += bias[n0 + c + 1];
            v.z += bias[n0 + c + 2];
            v.w += bias[n0 + c + 3];
            *(float4*)&Cext[(size_t)(m0 + r) * ldN + n0 + c] = v;
        }
    }
}

// ---------------- attention: one warp per (batch, head), fp16 in/out ----------------
// lane l owns head-dims (2l, 2l+1) via half2; math in fp32.
__global__ __launch_bounds__(256) void attn_kernel()
{
    int gwarp = blockIdx.x * 8 + (threadIdx.x >> 5);
    int lane = threadIdx.x & 31;
    if (gwarp >= BATCH * HEADS) return;
    int b = gwarp >> 3;
    int h = gwarp & 7;

    const __half* qb  = g_Qh  + (size_t)b * SEQ * DIM       + h * 64;
    const __half* kvb = g_KVh + (size_t)b * SEQ * (2 * DIM) + h * 64;

    float2 q[4], k[4], v[4];
#pragma unroll
    for (int i = 0; i < 4; i++) {
        q[i] = __half22float2(*(const __half2*)&qb[i * DIM + 2 * lane]);
        k[i] = __half22float2(*(const __half2*)&kvb[i * (2 * DIM) + 2 * lane]);
        v[i] = __half22float2(*(const __half2*)&kvb[i * (2 * DIM) + DIM + 2 * lane]);
    }

    float s[4][4];
#pragma unroll
    for (int i = 0; i < 4; i++) {
#pragma unroll
        for (int j = 0; j < 4; j++) {
            float p = q[i].x * k[j].x + q[i].y * k[j].y;
#pragma unroll
            for (int o = 16; o > 0; o >>= 1)
                p += __shfl_xor_sync(0xFFFFFFFFu, p, o);
            s[i][j] = p * SCALE_F;
        }
    }

#pragma unroll
    for (int i = 0; i < 4; i++) {
        int jm = 3 - i;                         // masked pair (dist = sqrt2)
        s[i][jm] = -(float)(jm + 1) * GAMMA_F;  // finite bias, stays in denominator

        float mx = fmaxf(fmaxf(s[i][0], s[i][1]), fmaxf(s[i][2], s[i][3]));
        float e[4], sum = 0.0f;
#pragma unroll
        for (int j = 0; j < 4; j++) { e[j] = expf(s[i][j] - mx); sum += e[j]; }
        float inv = 1.0f / sum;
        float p[4];
#pragma unroll
        for (int j = 0; j < 4; j++) p[j] = e[j] * inv;
        p[jm] = 0.0f;                           // post-softmax mask

        float o0 = 0.0f, o1 = 0.0f;
#pragma unroll
        for (int j = 0; j < 4; j++) { o0 += p[j] * v[j].x; o1 += p[j] * v[j].y; }

        __half2* dst = (__half2*)(g_AOh + (size_t)(b * SEQ + i) * DIM + h * 64 + 2 * lane);
        *dst = __floats2half2_rn(o0, o1);
    }
}

// ---------------- launch ----------------
extern "C" void kernel_launch(void* const* d_in, const int* in_sizes, int n_in,
                              void* d_out, int out_size)
{
    const float* x   = (const float*)d_in[0];
    const float* ctx = (const float*)d_in[1];
    const float* Wq  = (const float*)d_in[2];
    const float* bq  = (const float*)d_in[3];
    const float* Wkv = (const float*)d_in[4];
    const float* bkv = (const float*)d_in[5];
    const float* Wo  = (const float*)d_in[6];
    const float* bo  = (const float*)d_in[7];
    float* out = (float*)d_out;

    cudaFuncSetAttribute(gemm_mma, cudaFuncAttributeMaxDynamicSharedMemorySize, SMEM_BYTES);

    dim3 tb(32, 8);
    transpose_half<<<dim3(DIM / 32, DIM / 32), tb>>>(Wq, DIM, 0);
    transpose_half<<<dim3(DIM / 32, 2 * DIM / 32), tb>>>(Wkv, 2 * DIM, 1);
    transpose_half<<<dim3(DIM / 32, DIM / 32), tb>>>(Wo, DIM, 2);
    to_half<<<(ROWS * DIM / 4) / 256, 256>>>(x, 0);
    to_half<<<(ROWS * DIM / 4) / 256, 256>>>(ctx, 1);

    // Q = x @ Wq + bq (fp16 out)
    gemm_mma<<<dim3(DIM / BN, ROWS / BM), 256, SMEM_BYTES>>>(bq, nullptr, DIM, 0);
    // KV = ctx @ Wkv + bkv (fp16 out)
    gemm_mma<<<dim3(2 * DIM / BN, ROWS / BM), 256, SMEM_BYTES>>>(bkv, nullptr, 2 * DIM, 1);
    // attention (fp16 in/out)
    attn_kernel<<<BATCH * HEADS / 8, 256>>>();
    // out = AO @ Wo + bo (fp32 out)
    gemm_mma<<<dim3(DIM / BN, ROWS / BM), 256, SMEM_BYTES>>>(bo, out, DIM, 2);
}